// round 13
// baseline (speedup 1.0000x reference)
#include <cuda_runtime.h>
#include <math.h>
#include <stdint.h>

// ---------------- problem constants ----------------
#define BGR   128
#define NPER0 512
#define EPG   8192
#define EPGP  10240        // padded csr stride per graph
#define EE    (BGR*EPG)
#define N0    (BGR*NPER0)  // 65536
#define K1    410
#define K2    328
#define N1    (BGR*K1)     // 52480
#define HF    128
#define DOUT  10
#define BN_EPS 1e-5f

typedef unsigned long long u64;

// ---------------- static device scratch ----------------
__device__ float g_bufB[(size_t)N0*HF];   // X@W
__device__ float g_bufC[(size_t)N1*HF];   // hp1
__device__ float g_dinv[N0];
__device__ int   g_remap[N0];
__device__ int   g_rowbase[N0];           // LOCAL offset within graph's csr
__device__ int   g_rowcnt[N0];
__device__ int   g_csrsrc[(size_t)BGR*EPGP];  // s_local<<8 (smem byte offset)
__device__ u64   g_Wp1[64*HF];
__device__ u64   g_Wp2[64*HF];
__device__ float g_pool[3*BGR*HF];

__device__ __forceinline__ u64 ffma2(u64 a, u64 b, u64 c) {
    u64 d;
    asm("fma.rn.f32x2 %0, %1, %2, %3;" : "=l"(d) : "l"(a), "l"(b), "l"(c));
    return d;
}
__device__ __forceinline__ u64 fadd2(u64 a, u64 b) {
    u64 d;
    asm("add.rn.f32x2 %0, %1, %2;" : "=l"(d) : "l"(a), "l"(b));
    return d;
}

// ---------------- pack both weight matrices ----------------
__global__ void k_packW2(const float* __restrict__ W1, const float* __restrict__ W2,
                         u64* __restrict__ Wp1, u64* __restrict__ Wp2) {
    int i = blockIdx.x * blockDim.x + threadIdx.x;
    const int n = 64 * HF;
    if (i >= 2 * n) return;
    const float* W = (i < n) ? W1 : W2;
    u64* Wp = (i < n) ? Wp1 : Wp2;
    int j = (i < n) ? i : i - n;
    int kp = j >> 7, c = j & 127;
    u64 lo = __float_as_uint(W[(2 * kp) * HF + c]);
    u64 hi = __float_as_uint(W[(2 * kp + 1) * HF + c]);
    Wp[j] = lo | (hi << 32);
}

// ---------------- CSR build, 256 threads, carved from dynamic smem ------------
__device__ __forceinline__
void dev_csr256(int g, const int* __restrict__ src, const int* __restrict__ dst,
                const int* __restrict__ remap, int nper_dst,
                int* __restrict__ row_base, int* __restrict__ row_cnt,
                int* __restrict__ csr, float* __restrict__ dinv, char* dsm) {
    unsigned* ed  = (unsigned*)dsm;
    int* cnt  = (int*)(dsm + 32768);
    int* off  = cnt + 512;
    int* cur  = off + 512;
    int* rms  = cur + 512;
    int* wsum8 = rms + 512;
    int tid = threadIdx.x, lane = tid & 31, wid = tid >> 5;
    cnt[tid] = 0; cnt[tid + 256] = 0;
    cur[tid] = 0; cur[tid + 256] = 0;
    if (remap) {
        rms[tid]       = remap[g * NPER0 + tid];
        rms[tid + 256] = remap[g * NPER0 + tid + 256];
    }
    __syncthreads();
    int ebase = g * EPG, gdst = g * nper_dst;
    for (int e = tid; e < EPG; e += 256) {
        int s = src[ebase + e] - g * NPER0;
        int d = dst[ebase + e] - g * NPER0;
        unsigned pk = 0xFFFFFFFFu;
        if (remap) {
            int rs = rms[s], rd = rms[d];
            if ((rs | rd) >= 0)
                pk = ((unsigned)(rs - gdst) << 16) | (unsigned)(rd - gdst);
        } else {
            pk = ((unsigned)s << 16) | (unsigned)d;
        }
        ed[e] = pk;
        if (pk != 0xFFFFFFFFu) atomicAdd(&cnt[pk & 0xFFFFu], 1);
    }
    __syncthreads();
    int c0 = cnt[2 * tid], c1 = cnt[2 * tid + 1];
    int pc0 = (c0 + 3) & ~3, pc1 = (c1 + 3) & ~3;
    int v = pc0 + pc1;
    #pragma unroll
    for (int d2 = 1; d2 < 32; d2 <<= 1) {
        int t = __shfl_up_sync(0xFFFFFFFFu, v, d2);
        if (lane >= d2) v += t;
    }
    if (lane == 31) wsum8[wid] = v;
    __syncthreads();
    if (tid < 8) {
        int w = wsum8[tid];
        #pragma unroll
        for (int d2 = 1; d2 < 8; d2 <<= 1) {
            int t = __shfl_up_sync(0xFFu, w, d2);
            if (tid >= d2) w += t;
        }
        wsum8[tid] = w;
    }
    __syncthreads();
    int excl = v - (pc0 + pc1) + ((wid > 0) ? wsum8[wid - 1] : 0);
    int ebp = g * EPGP;
    int n0 = 2 * tid, n1 = 2 * tid + 1;
    if (n0 < nper_dst) {
        row_cnt[gdst + n0]  = c0;
        row_base[gdst + n0] = excl;
        dinv[gdst + n0]     = rsqrtf(1.0f + (float)c0);
    }
    if (n1 < nper_dst) {
        row_cnt[gdst + n1]  = c1;
        row_base[gdst + n1] = excl + pc0;
        dinv[gdst + n1]     = rsqrtf(1.0f + (float)c1);
    }
    off[n0] = excl; off[n1] = excl + pc0;
    __syncthreads();
    for (int e = tid; e < EPG; e += 256) {
        unsigned pk = ed[e];
        if (pk != 0xFFFFFFFFu) {
            int d = pk & 0xFFFFu, s = pk >> 16;
            int p = atomicAdd(&cur[d], 1);
            csr[ebp + off[d] + p] = s << 8;
        }
    }
}

// ---------------- GEMM v4: 128-row tile, 256 thr, warp = 16 rows x 2 cols -----
// Cuts W bytes per FMA 4x vs v3: per kp one LDG.128 covers both lane columns.
// X reads are warp-uniform smem broadcasts (cheap wavefronts).
__device__ __forceinline__
void dev_gemm128(int tile, const float* __restrict__ X, const u64* __restrict__ Wp,
                 float* __restrict__ Y, float (*Xs)[HF]) {
    int row0 = tile * 128;
    int tid = threadIdx.x;
    #pragma unroll
    for (int j = 0; j < 16; j++) {
        int idx = j * 256 + tid;                 // 4096 float4 = 128x128 floats
        int r = idx >> 5, c4 = idx & 31;
        float4 v = *(const float4*)(X + (size_t)(row0 + r) * HF + c4 * 4);
        *(float4*)(&Xs[r][c4 * 4]) = v;
    }
    __syncthreads();
    int wid = tid >> 5, lane = tid & 31;
    int r0 = wid * 16;
    #pragma unroll 1
    for (int ch = 0; ch < 2; ch++) {
        int c0 = ch * 64 + lane * 2;
        u64 accP[16], accQ[16];
        #pragma unroll
        for (int i = 0; i < 16; i++) { accP[i] = 0; accQ[i] = 0; }
        const u64* wp = Wp + c0;
        #pragma unroll 1
        for (int kp4 = 0; kp4 < 16; kp4++) {
            ulonglong2 w0 = *(const ulonglong2*)(wp + (size_t)(kp4 * 4    ) * HF);
            ulonglong2 w1 = *(const ulonglong2*)(wp + (size_t)(kp4 * 4 + 1) * HF);
            ulonglong2 w2 = *(const ulonglong2*)(wp + (size_t)(kp4 * 4 + 2) * HF);
            ulonglong2 w3 = *(const ulonglong2*)(wp + (size_t)(kp4 * 4 + 3) * HF);
            #pragma unroll
            for (int i = 0; i < 16; i++) {
                ulonglong2 xa = *(const ulonglong2*)(&Xs[r0 + i][kp4 * 8]);
                ulonglong2 xb = *(const ulonglong2*)(&Xs[r0 + i][kp4 * 8 + 4]);
                accP[i] = ffma2(xa.x, w0.x, accP[i]);
                accQ[i] = ffma2(xa.x, w0.y, accQ[i]);
                accP[i] = ffma2(xa.y, w1.x, accP[i]);
                accQ[i] = ffma2(xa.y, w1.y, accQ[i]);
                accP[i] = ffma2(xb.x, w2.x, accP[i]);
                accQ[i] = ffma2(xb.x, w2.y, accQ[i]);
                accP[i] = ffma2(xb.y, w3.x, accP[i]);
                accQ[i] = ffma2(xb.y, w3.y, accQ[i]);
            }
        }
        #pragma unroll
        for (int i = 0; i < 16; i++) {
            float2 p = *(float2*)&accP[i];
            float2 q = *(float2*)&accQ[i];
            float2 o = make_float2(p.x + p.y, q.x + q.y);
            *(float2*)(Y + (size_t)(row0 + r0 + i) * HF + c0) = o;
        }
    }
}

// ---------------- layer-0 combined: csr0 | pooled_x | gemm0 -------------------
__global__ void __launch_bounds__(256, 2)
k_comb_g0(const float* __restrict__ x, const u64* __restrict__ Wp1,
          float* __restrict__ bufB, float* __restrict__ P0,
          const int* __restrict__ src, const int* __restrict__ dst,
          int* __restrict__ rowbase, int* __restrict__ rowcnt,
          int* __restrict__ csr, float* __restrict__ dinv) {
    extern __shared__ char dsm[];
    int bid = blockIdx.x;
    if (bid < BGR) {
        dev_csr256(bid, src, dst, nullptr, NPER0, rowbase, rowcnt, csr, dinv, dsm);
    } else if (bid < 2 * BGR) {
        int g = bid - BGR;
        float* red = (float*)dsm;
        int f = threadIdx.x & 127, q = threadIdx.x >> 7;
        const float* base = x + (size_t)g * NPER0 * HF + f;
        float acc = 0.f;
        for (int r = q; r < NPER0; r += 2) acc += base[(size_t)r * HF];
        red[q * HF + f] = acc;
        __syncthreads();
        if (q == 0) P0[g * HF + f] = red[f] + red[HF + f];
    } else {
        dev_gemm128(bid - 2 * BGR, x, Wp1, bufB, (float(*)[HF])dsm);
    }
}

// ---------------- layer-1 combined: csr1 | gemm1 -------------------
__global__ void __launch_bounds__(256, 2)
k_comb_g1(const float* __restrict__ X, const u64* __restrict__ Wp2,
          float* __restrict__ Y,
          const int* __restrict__ src, const int* __restrict__ dst,
          const int* __restrict__ remap,
          int* __restrict__ rowbase, int* __restrict__ rowcnt,
          int* __restrict__ csr, float* __restrict__ dinv) {
    extern __shared__ char dsm[];
    int bid = blockIdx.x;
    if (bid < BGR) {
        dev_csr256(bid, src, dst, remap, K1, rowbase, rowcnt, csr, dinv, dsm);
    } else {
        dev_gemm128(bid - BGR, X, Wp2, Y, (float(*)[HF])dsm);
    }
}

// ================= MEGA v7: 1024 threads fully used in scalar phases ==========
__global__ void __launch_bounds__(1024, 1)
k_mega(const float* __restrict__ H,
       const int* __restrict__ csr,
       const int* __restrict__ row_base, const int* __restrict__ row_cnt,
       const float* __restrict__ dinv,
       const float* __restrict__ bias, const float* __restrict__ sW,
       const float* __restrict__ sb,
       const float* __restrict__ bg, const float* __restrict__ bb,
       const float* __restrict__ bm, const float* __restrict__ bv,
       int nper, int k,
       int* __restrict__ remap,
       float* __restrict__ hp /*null for layer 1*/, float* __restrict__ pooled,
       int write_remap,
       const float* __restrict__ pool0, const float* __restrict__ pool1,
       const float* __restrict__ lW0, const float* __restrict__ lb0,
       const float* __restrict__ lW1, const float* __restrict__ lb1,
       const float* __restrict__ lW2, const float* __restrict__ lb2,
       float* __restrict__ finout) {
    extern __shared__ float stage[];   // [nper*64 floats stage][EPGP ints csr_s]
    __shared__ float di_s[512];
    __shared__ float tdi_s[512];
    __shared__ float hsdi_s[512];
    __shared__ float sc_s[512];
    __shared__ float tn_s[512];
    __shared__ int   inv_s[512];
    __shared__ int   rb_s[512];
    __shared__ int   rc_s[512];
    __shared__ int   wsum16[16];
    __shared__ int   scr[1024];
    __shared__ float bnA[HF];
    __shared__ float bnC[HF];
    __shared__ float pool_s[HF];
    __shared__ float bs_sh;
    float* fpart = (float*)scr;

    int g = blockIdx.x, tid = threadIdx.x;
    int lane = tid & 31, wid = tid >> 5;
    int node = tid & 511, half = tid >> 9;
    int gbase = g * nper;
    int* csr_sm = (int*)(stage + nper * 64);

    if (tid < HF) {
        float A = bg[tid] * rsqrtf(bv[tid] + BN_EPS);
        bnA[tid] = A;
        bnC[tid] = bb[tid] - A * bm[tid];
        pool_s[tid] = 0.f;
    }
    if (tid < 512) {
        bool in = tid < nper;
        di_s[tid] = in ? dinv[gbase + tid] : 0.f;
        rb_s[tid] = in ? row_base[gbase + tid] : 0;
        rc_s[tid] = in ? row_cnt[gbase + tid] : 0;
    }
    if (wid == 31) {   // bs = conv_bias · score_W
        float a = 0.f;
        #pragma unroll
        for (int f = lane; f < HF; f += 32) a += bias[f] * sW[f];
        #pragma unroll
        for (int off = 16; off > 0; off >>= 1) a += __shfl_down_sync(0xFFFFFFFFu, a, off);
        if (lane == 0) bs_sh = a;
    }
    {
        int4* dstv = (int4*)csr_sm;
        const int4* srcv = (const int4*)(csr + (size_t)g * EPGP);
        for (int i = tid; i < EPGP / 4; i += 1024) dstv[i] = srcv[i];
    }
    __syncthreads();

    // ---- t-pass ----
    {
        float4 wv4 = *(const float4*)(sW + lane * 4);
        for (int v = wid; v < nper; v += 32) {
            float4 h = *(const float4*)(H + (size_t)(gbase + v) * HF + lane * 4);
            float p = h.x * wv4.x + h.y * wv4.y + h.z * wv4.z + h.w * wv4.w;
            #pragma unroll
            for (int off = 16; off > 0; off >>= 1) p += __shfl_down_sync(0xFFFFFFFFu, p, off);
            if (lane == 0) tdi_s[v] = p * di_s[v];
        }
    }
    __syncthreads();

    // ---- hs sweep (2 threads per node) ----
    {
        float part = 0.f;
        if (node < nper) {
            int base = rb_s[node], cnt = rc_s[node];
            const int* cp = csr_sm + base;
            const char* hb = (const char*)tdi_s;
            for (int e = half * 4; e + 4 <= cnt; e += 8) {
                int4 o = *(const int4*)(cp + e);
                part += *(const float*)(hb + (o.x >> 6)) + *(const float*)(hb + (o.y >> 6))
                      + *(const float*)(hb + (o.z >> 6)) + *(const float*)(hb + (o.w >> 6));
            }
            if (half == 0)
                for (int e = cnt & ~3; e < cnt; e++)
                    part += *(const float*)(hb + (cp[e] >> 6));
        }
        fpart[tid] = part;
        __syncthreads();
        if (tid < nper) {
            float di = di_s[tid];
            float hs = (fpart[tid] + fpart[tid + 512] + tdi_s[tid]) * di + bs_sh;
            hsdi_s[tid] = hs * di;
        } else if (tid < 512) hsdi_s[tid] = 0.f;
        __syncthreads();
    }

    // ---- score sweep (split) ----
    float scv = -1e30f;
    {
        float part = 0.f;
        if (node < nper) {
            int base = rb_s[node], cnt = rc_s[node];
            const int* cp = csr_sm + base;
            const char* hb = (const char*)hsdi_s;
            for (int e = half * 4; e + 4 <= cnt; e += 8) {
                int4 o = *(const int4*)(cp + e);
                part += *(const float*)(hb + (o.x >> 6)) + *(const float*)(hb + (o.y >> 6))
                      + *(const float*)(hb + (o.z >> 6)) + *(const float*)(hb + (o.w >> 6));
            }
            if (half == 0)
                for (int e = cnt & ~3; e < cnt; e++)
                    part += *(const float*)(hb + (cp[e] >> 6));
        }
        fpart[tid] = part;
        __syncthreads();
        if (tid < nper) {
            float di = di_s[tid];
            scv = (fpart[tid] + fpart[tid + 512] + hsdi_s[tid]) * di + sb[0];
        }
        if (tid < 512) sc_s[tid] = scv;
        __syncthreads();
    }

    // ---- rank (split halves) ----
    int kept = 0;
    {
        float si = sc_s[node];
        int r = 0;
        const float4* sc4 = (const float4*)sc_s;
        int j0 = half * 64;
        for (int j4 = j0; j4 < j0 + 64; j4++) {
            float4 pj = sc4[j4];
            int b4 = 4 * j4;
            r += (pj.x > si) || (pj.x == si && (b4)     < node);
            r += (pj.y > si) || (pj.y == si && (b4 + 1) < node);
            r += (pj.z > si) || (pj.z == si && (b4 + 2) < node);
            r += (pj.w > si) || (pj.w == si && (b4 + 3) < node);
        }
        scr[tid] = r;
        __syncthreads();
        if (tid < 512) {
            int rank = scr[tid] + scr[tid + 512];
            kept = (tid < nper && rank < k) ? 1 : 0;
        }
    }

    // ---- warp-shuffle scan over 512 ----
    int v = kept;
    if (tid < 512) {
        #pragma unroll
        for (int d2 = 1; d2 < 32; d2 <<= 1) {
            int t = __shfl_up_sync(0xFFFFFFFFu, v, d2);
            if (lane >= d2) v += t;
        }
        if (lane == 31) wsum16[wid] = v;
    }
    __syncthreads();
    if (tid < 16) {
        int w = wsum16[tid];
        #pragma unroll
        for (int d2 = 1; d2 < 16; d2 <<= 1) {
            int t = __shfl_up_sync(0xFFFFu, w, d2);
            if (tid >= d2) w += t;
        }
        wsum16[tid] = w;
    }
    __syncthreads();
    if (tid < nper) {
        int incl = v + ((wid > 0) ? wsum16[wid - 1] : 0);
        int pos = incl - 1;
        if (write_remap) remap[gbase + tid] = kept ? (g * k + pos) : -1;
        if (kept) {
            inv_s[pos] = tid;
            tn_s[pos]  = tanhf(scv);
        }
    }
    __syncthreads();

    // ---- two feature-chunk passes: aggregate KEPT rows only ----
    #pragma unroll 1
    for (int cf = 0; cf < HF; cf += 64) {
        for (int i2 = tid; i2 < nper * 16; i2 += 1024) {
            int row = i2 >> 4, f4 = (i2 & 15) * 4;
            float4 vv = *(const float4*)(H + (size_t)(gbase + row) * HF + cf + f4);
            float d = di_s[row];
            vv.x *= d; vv.y *= d; vv.z *= d; vv.w *= d;
            *(float4*)(&stage[row * 64 + f4]) = vv;
        }
        __syncthreads();
        int fp = 2 * lane;
        const char* sf = (const char*)stage + fp * 4;
        float2 bp = *(const float2*)(bias + cf + fp);
        float2 bA = *(const float2*)(bnA + cf + fp);
        float2 bC = *(const float2*)(bnC + cf + fp);
        float s0 = 0.f, s1 = 0.f;
        for (int rn = wid; rn < k; rn += 32) {
            int old = inv_s[rn];
            int base = rb_s[old], cnt = rc_s[old];
            const int* cp = csr_sm + base;
            u64 A0 = *(const u64*)(sf + old * 256);
            u64 A1 = 0, A2 = 0, A3 = 0;
            int e = 0;
            for (; e + 8 <= cnt; e += 8) {
                int4 o0 = *(const int4*)(cp + e);
                int4 o1 = *(const int4*)(cp + e + 4);
                A0 = fadd2(A0, *(const u64*)(sf + o0.x));
                A1 = fadd2(A1, *(const u64*)(sf + o0.y));
                A2 = fadd2(A2, *(const u64*)(sf + o0.z));
                A3 = fadd2(A3, *(const u64*)(sf + o0.w));
                A0 = fadd2(A0, *(const u64*)(sf + o1.x));
                A1 = fadd2(A1, *(const u64*)(sf + o1.y));
                A2 = fadd2(A2, *(const u64*)(sf + o1.z));
                A3 = fadd2(A3, *(const u64*)(sf + o1.w));
            }
            for (; e + 4 <= cnt; e += 4) {
                int4 o = *(const int4*)(cp + e);
                A0 = fadd2(A0, *(const u64*)(sf + o.x));
                A1 = fadd2(A1, *(const u64*)(sf + o.y));
                A2 = fadd2(A2, *(const u64*)(sf + o.z));
                A3 = fadd2(A3, *(const u64*)(sf + o.w));
            }
            for (; e < cnt; e++)
                A0 = fadd2(A0, *(const u64*)(sf + cp[e]));
            A0 = fadd2(fadd2(A0, A1), fadd2(A2, A3));
            float2 r0 = *(float2*)&A0;
            float d = di_s[old];
            float tv = tn_s[rn];
            float o0 = r0.x * d + bp.x;
            float o1 = r0.y * d + bp.y;
            float q0 = fmaxf(bA.x * (o0 * tv) + bC.x, 0.f);
            float q1 = fmaxf(bA.y * (o1 * tv) + bC.y, 0.f);
            if (hp)
                *(float2*)(hp + ((size_t)g * k + rn) * HF + cf + fp) = make_float2(q0, q1);
            s0 += q0; s1 += q1;
        }
        atomicAdd(&pool_s[cf + fp],     s0);
        atomicAdd(&pool_s[cf + fp + 1], s1);
        __syncthreads();
    }
    if (tid < HF) pooled[g * HF + tid] = pool_s[tid];

    // ---- fused readout (layer 1 only) ----
    if (finout && wid < DOUT) {
        int o = wid;
        const float* p0g = pool0 + g * HF;
        const float* p1g = pool1 + g * HF;
        const float* w0 = lW0 + o * HF;
        const float* w1 = lW1 + o * HF;
        const float* w2 = lW2 + o * HF;
        float a = 0.f;
        #pragma unroll
        for (int f = lane; f < HF; f += 32)
            a += p0g[f] * w0[f] + p1g[f] * w1[f] + pool_s[f] * w2[f];
        #pragma unroll
        for (int off = 16; off > 0; off >>= 1) a += __shfl_down_sync(0xFFFFFFFFu, a, off);
        if (lane == 0) finout[g * DOUT + o] = a + lb0[o] + lb1[o] + lb2[o];
    }
}

// ---------------- host launch ----------------
extern "C" void kernel_launch(void* const* d_in, const int* in_sizes, int n_in,
                              void* d_out, int out_size) {
    const float* x        = (const float*)d_in[0];
    const int*   ei       = (const int*)  d_in[1];
    const float* conv1_W  = (const float*)d_in[2];
    const float* conv1_b  = (const float*)d_in[3];
    const float* conv2_W  = (const float*)d_in[4];
    const float* conv2_b  = (const float*)d_in[5];
    const float* score1_W = (const float*)d_in[6];
    const float* score1_b = (const float*)d_in[7];
    const float* score2_W = (const float*)d_in[8];
    const float* score2_b = (const float*)d_in[9];
    const float* bn1_g    = (const float*)d_in[10];
    const float* bn1_b    = (const float*)d_in[11];
    const float* bn1_m    = (const float*)d_in[12];
    const float* bn1_v    = (const float*)d_in[13];
    const float* bn2_g    = (const float*)d_in[14];
    const float* bn2_b    = (const float*)d_in[15];
    const float* bn2_m    = (const float*)d_in[16];
    const float* bn2_v    = (const float*)d_in[17];
    const float* lin0_W   = (const float*)d_in[18];
    const float* lin0_b   = (const float*)d_in[19];
    const float* lin1_W   = (const float*)d_in[20];
    const float* lin1_b   = (const float*)d_in[21];
    const float* lin2_W   = (const float*)d_in[22];
    const float* lin2_b   = (const float*)d_in[23];
    float* out = (float*)d_out;

    const int* src0 = ei;
    const int* dst0 = ei + EE;

    float *bufB, *bufC, *dinv, *pool;
    int *remap, *rowbase, *rowcnt, *csrsrc;
    u64 *wp1, *wp2;
    cudaGetSymbolAddress((void**)&bufB,   g_bufB);
    cudaGetSymbolAddress((void**)&bufC,   g_bufC);
    cudaGetSymbolAddress((void**)&dinv,   g_dinv);
    cudaGetSymbolAddress((void**)&remap,  g_remap);
    cudaGetSymbolAddress((void**)&rowbase,g_rowbase);
    cudaGetSymbolAddress((void**)&rowcnt, g_rowcnt);
    cudaGetSymbolAddress((void**)&csrsrc, g_csrsrc);
    cudaGetSymbolAddress((void**)&wp1,    g_Wp1);
    cudaGetSymbolAddress((void**)&wp2,    g_Wp2);
    cudaGetSymbolAddress((void**)&pool,   g_pool);

    const int COMB_SMEM  = 128 * HF * (int)sizeof(float);  // 64 KB (gemm Xs / csr carve)
    const int MEGA_SMEM0 = (NPER0 * 64) * 4 + EPGP * 4;    // 168 KB
    const int MEGA_SMEM1 = (K1 * 64) * 4 + EPGP * 4;       // ~142.5 KB
    cudaFuncSetAttribute(k_mega, cudaFuncAttributeMaxDynamicSharedMemorySize, MEGA_SMEM0);
    cudaFuncSetAttribute(k_comb_g0, cudaFuncAttributeMaxDynamicSharedMemorySize, COMB_SMEM);
    cudaFuncSetAttribute(k_comb_g1, cudaFuncAttributeMaxDynamicSharedMemorySize, COMB_SMEM);

    k_packW2<<<(2 * 64 * HF + 255) / 256, 256>>>(conv1_W, conv2_W, wp1, wp2);

    // ---------- layer 0: csr0 | pooled_x | gemm0 in one launch ----------
    k_comb_g0<<<2 * BGR + N0 / 128, 256, COMB_SMEM>>>(x, wp1, bufB, pool,
                                                      src0, dst0, rowbase, rowcnt,
                                                      csrsrc, dinv);
    k_mega<<<BGR, 1024, MEGA_SMEM0>>>(bufB, csrsrc, rowbase, rowcnt, dinv,
                                      conv1_b, score1_W, score1_b,
                                      bn1_g, bn1_b, bn1_m, bn1_v,
                                      NPER0, K1, remap, bufC,
                                      pool + BGR * HF, 1,
                                      nullptr, nullptr, nullptr, nullptr,
                                      nullptr, nullptr, nullptr, nullptr, nullptr);

    // ---------- layer 1: csr1 | gemm1 in one launch; readout fused in mega ----
    k_comb_g1<<<BGR + N1 / 128, 256, COMB_SMEM>>>(bufC, wp2, bufB,
                                                  src0, dst0, remap, rowbase, rowcnt,
                                                  csrsrc, dinv);
    k_mega<<<BGR, 1024, MEGA_SMEM1>>>(bufB, csrsrc, rowbase, rowcnt, dinv,
                                      conv2_b, score2_W, score2_b,
                                      bn2_g, bn2_b, bn2_m, bn2_v,
                                      K1, K2, remap, nullptr,
                                      pool + 2 * BGR * HF, 0,
                                      pool, pool + BGR * HF,
                                      lin0_W, lin0_b, lin1_W, lin1_b, lin2_W, lin2_b,
                                      out);
}

// round 14
// speedup vs baseline: 1.0873x; 1.0873x over previous
#include <cuda_runtime.h>
#include <math.h>
#include <stdint.h>

// ---------------- problem constants ----------------
#define BGR   128
#define NPER0 512
#define EPG   8192
#define EPGP  10240        // padded csr stride per graph
#define EE    (BGR*EPG)
#define N0    (BGR*NPER0)  // 65536
#define K1    410
#define K2    328
#define N1    (BGR*K1)     // 52480
#define HF    128
#define DOUT  10
#define BN_EPS 1e-5f

typedef unsigned long long u64;

// ---------------- static device scratch ----------------
__device__ float g_bufB[(size_t)N0*HF];   // X@W
__device__ float g_bufC[(size_t)N1*HF];   // hp1
__device__ float g_dinv[N0];
__device__ int   g_remap[N0];
__device__ int   g_rowbase[N0];           // LOCAL offset within graph's csr
__device__ int   g_rowcnt[N0];
__device__ int   g_csrsrc[(size_t)BGR*EPGP];  // s_local<<8 (smem byte offset)
__device__ u64   g_Wp1[64*HF];
__device__ u64   g_Wp2[64*HF];
__device__ float g_pool[3*BGR*HF];

__device__ __forceinline__ u64 ffma2(u64 a, u64 b, u64 c) {
    u64 d;
    asm("fma.rn.f32x2 %0, %1, %2, %3;" : "=l"(d) : "l"(a), "l"(b), "l"(c));
    return d;
}
__device__ __forceinline__ u64 fadd2(u64 a, u64 b) {
    u64 d;
    asm("add.rn.f32x2 %0, %1, %2;" : "=l"(d) : "l"(a), "l"(b));
    return d;
}

// ---------------- pack both weight matrices ----------------
__global__ void k_packW2(const float* __restrict__ W1, const float* __restrict__ W2,
                         u64* __restrict__ Wp1, u64* __restrict__ Wp2) {
    int i = blockIdx.x * blockDim.x + threadIdx.x;
    const int n = 64 * HF;
    if (i >= 2 * n) return;
    const float* W = (i < n) ? W1 : W2;
    u64* Wp = (i < n) ? Wp1 : Wp2;
    int j = (i < n) ? i : i - n;
    int kp = j >> 7, c = j & 127;
    u64 lo = __float_as_uint(W[(2 * kp) * HF + c]);
    u64 hi = __float_as_uint(W[(2 * kp + 1) * HF + c]);
    Wp[j] = lo | (hi << 32);
}

// ---------------- CSR build, 256 threads, carved from dynamic smem ------------
__device__ __forceinline__
void dev_csr256(int g, const int* __restrict__ src, const int* __restrict__ dst,
                const int* __restrict__ remap, int nper_dst,
                int* __restrict__ row_base, int* __restrict__ row_cnt,
                int* __restrict__ csr, float* __restrict__ dinv, char* dsm) {
    unsigned* ed  = (unsigned*)dsm;
    int* cnt  = (int*)(dsm + 32768);
    int* off  = cnt + 512;
    int* cur  = off + 512;
    int* rms  = cur + 512;
    int* wsum8 = rms + 512;
    int tid = threadIdx.x, lane = tid & 31, wid = tid >> 5;
    cnt[tid] = 0; cnt[tid + 256] = 0;
    cur[tid] = 0; cur[tid + 256] = 0;
    if (remap) {
        rms[tid]       = remap[g * NPER0 + tid];
        rms[tid + 256] = remap[g * NPER0 + tid + 256];
    }
    __syncthreads();
    int ebase = g * EPG, gdst = g * nper_dst;
    for (int e = tid; e < EPG; e += 256) {
        int s = src[ebase + e] - g * NPER0;
        int d = dst[ebase + e] - g * NPER0;
        unsigned pk = 0xFFFFFFFFu;
        if (remap) {
            int rs = rms[s], rd = rms[d];
            if ((rs | rd) >= 0)
                pk = ((unsigned)(rs - gdst) << 16) | (unsigned)(rd - gdst);
        } else {
            pk = ((unsigned)s << 16) | (unsigned)d;
        }
        ed[e] = pk;
        if (pk != 0xFFFFFFFFu) atomicAdd(&cnt[pk & 0xFFFFu], 1);
    }
    __syncthreads();
    int c0 = cnt[2 * tid], c1 = cnt[2 * tid + 1];
    int pc0 = (c0 + 3) & ~3, pc1 = (c1 + 3) & ~3;
    int v = pc0 + pc1;
    #pragma unroll
    for (int d2 = 1; d2 < 32; d2 <<= 1) {
        int t = __shfl_up_sync(0xFFFFFFFFu, v, d2);
        if (lane >= d2) v += t;
    }
    if (lane == 31) wsum8[wid] = v;
    __syncthreads();
    if (tid < 8) {
        int w = wsum8[tid];
        #pragma unroll
        for (int d2 = 1; d2 < 8; d2 <<= 1) {
            int t = __shfl_up_sync(0xFFu, w, d2);
            if (tid >= d2) w += t;
        }
        wsum8[tid] = w;
    }
    __syncthreads();
    int excl = v - (pc0 + pc1) + ((wid > 0) ? wsum8[wid - 1] : 0);
    int ebp = g * EPGP;
    int n0 = 2 * tid, n1 = 2 * tid + 1;
    if (n0 < nper_dst) {
        row_cnt[gdst + n0]  = c0;
        row_base[gdst + n0] = excl;
        dinv[gdst + n0]     = rsqrtf(1.0f + (float)c0);
    }
    if (n1 < nper_dst) {
        row_cnt[gdst + n1]  = c1;
        row_base[gdst + n1] = excl + pc0;
        dinv[gdst + n1]     = rsqrtf(1.0f + (float)c1);
    }
    off[n0] = excl; off[n1] = excl + pc0;
    __syncthreads();
    for (int e = tid; e < EPG; e += 256) {
        unsigned pk = ed[e];
        if (pk != 0xFFFFFFFFu) {
            int d = pk & 0xFFFFu, s = pk >> 16;
            int p = atomicAdd(&cur[d], 1);
            csr[ebp + off[d] + p] = s << 8;
        }
    }
}

// ---------------- GEMM v3: 64-row tile, 256 thr, warp = 8 rows x 4 cols -------
__device__ __forceinline__
void dev_gemm(int tile, const float* __restrict__ X, const u64* __restrict__ Wp,
              float* __restrict__ Y, float (*Xs)[HF]) {
    int row0 = tile * 64;
    int tid = threadIdx.x;
    #pragma unroll
    for (int j = 0; j < 8; j++) {
        int idx = j * 256 + tid;
        int r = idx >> 5, c4 = idx & 31;
        float4 v = *(const float4*)(X + (size_t)(row0 + r) * HF + c4 * 4);
        *(float4*)(&Xs[r][c4 * 4]) = v;
    }
    __syncthreads();
    int wid = tid >> 5, lane = tid & 31;
    int r0 = wid * 8, c0 = lane * 4;
    u64 acc[8][4] = {};
    const u64* wp = Wp + c0;
    #pragma unroll 1
    for (int kp4 = 0; kp4 < 16; kp4++) {
        const u64* wb = wp + (size_t)(kp4 * 4) * HF;
        ulonglong2 wA0 = *(const ulonglong2*)(wb);
        ulonglong2 wB0 = *(const ulonglong2*)(wb + 2);
        ulonglong2 wA1 = *(const ulonglong2*)(wb + HF);
        ulonglong2 wB1 = *(const ulonglong2*)(wb + HF + 2);
        ulonglong2 wA2 = *(const ulonglong2*)(wb + 2 * HF);
        ulonglong2 wB2 = *(const ulonglong2*)(wb + 2 * HF + 2);
        ulonglong2 wA3 = *(const ulonglong2*)(wb + 3 * HF);
        ulonglong2 wB3 = *(const ulonglong2*)(wb + 3 * HF + 2);
        #pragma unroll
        for (int i = 0; i < 8; i++) {
            ulonglong2 xa = *(const ulonglong2*)(&Xs[r0 + i][kp4 * 8]);
            ulonglong2 xb = *(const ulonglong2*)(&Xs[r0 + i][kp4 * 8 + 4]);
            acc[i][0] = ffma2(xa.x, wA0.x, acc[i][0]);
            acc[i][1] = ffma2(xa.x, wA0.y, acc[i][1]);
            acc[i][2] = ffma2(xa.x, wB0.x, acc[i][2]);
            acc[i][3] = ffma2(xa.x, wB0.y, acc[i][3]);
            acc[i][0] = ffma2(xa.y, wA1.x, acc[i][0]);
            acc[i][1] = ffma2(xa.y, wA1.y, acc[i][1]);
            acc[i][2] = ffma2(xa.y, wB1.x, acc[i][2]);
            acc[i][3] = ffma2(xa.y, wB1.y, acc[i][3]);
            acc[i][0] = ffma2(xb.x, wA2.x, acc[i][0]);
            acc[i][1] = ffma2(xb.x, wA2.y, acc[i][1]);
            acc[i][2] = ffma2(xb.x, wB2.x, acc[i][2]);
            acc[i][3] = ffma2(xb.x, wB2.y, acc[i][3]);
            acc[i][0] = ffma2(xb.y, wA3.x, acc[i][0]);
            acc[i][1] = ffma2(xb.y, wA3.y, acc[i][1]);
            acc[i][2] = ffma2(xb.y, wB3.x, acc[i][2]);
            acc[i][3] = ffma2(xb.y, wB3.y, acc[i][3]);
        }
    }
    #pragma unroll
    for (int i = 0; i < 8; i++) {
        int r = row0 + r0 + i;
        float2 p0 = *(float2*)&acc[i][0];
        float2 p1 = *(float2*)&acc[i][1];
        float2 p2 = *(float2*)&acc[i][2];
        float2 p3 = *(float2*)&acc[i][3];
        float4 o = make_float4(p0.x + p0.y, p1.x + p1.y, p2.x + p2.y, p3.x + p3.y);
        *(float4*)(Y + (size_t)r * HF + c0) = o;
    }
}

// ---------------- layer-0 combined: csr0 | pooled_x | gemm0 -------------------
__global__ void __launch_bounds__(256, 2)
k_comb_g0(const float* __restrict__ x, const u64* __restrict__ Wp1,
          float* __restrict__ bufB, float* __restrict__ P0,
          const int* __restrict__ src, const int* __restrict__ dst,
          int* __restrict__ rowbase, int* __restrict__ rowcnt,
          int* __restrict__ csr, float* __restrict__ dinv) {
    extern __shared__ char dsm[];
    int bid = blockIdx.x;
    if (bid < BGR) {
        dev_csr256(bid, src, dst, nullptr, NPER0, rowbase, rowcnt, csr, dinv, dsm);
    } else if (bid < 2 * BGR) {
        int g = bid - BGR;
        float* red = (float*)dsm;
        int f = threadIdx.x & 127, q = threadIdx.x >> 7;
        const float* base = x + (size_t)g * NPER0 * HF + f;
        float acc = 0.f;
        for (int r = q; r < NPER0; r += 2) acc += base[(size_t)r * HF];
        red[q * HF + f] = acc;
        __syncthreads();
        if (q == 0) P0[g * HF + f] = red[f] + red[HF + f];
    } else {
        dev_gemm(bid - 2 * BGR, x, Wp1, bufB, (float(*)[HF])dsm);
    }
}

// ---------------- layer-1 combined: csr1 | gemm1 -------------------
__global__ void __launch_bounds__(256, 2)
k_comb_g1(const float* __restrict__ X, const u64* __restrict__ Wp2,
          float* __restrict__ Y,
          const int* __restrict__ src, const int* __restrict__ dst,
          const int* __restrict__ remap,
          int* __restrict__ rowbase, int* __restrict__ rowcnt,
          int* __restrict__ csr, float* __restrict__ dinv) {
    extern __shared__ char dsm[];
    int bid = blockIdx.x;
    if (bid < BGR) {
        dev_csr256(bid, src, dst, remap, K1, rowbase, rowcnt, csr, dinv, dsm);
    } else {
        dev_gemm(bid - BGR, X, Wp2, Y, (float(*)[HF])dsm);
    }
}

// ================= MEGA v8: chunk-0 staged early (overlaps scalar phases) =====
__global__ void __launch_bounds__(1024, 1)
k_mega(const float* __restrict__ H,
       const int* __restrict__ csr,
       const int* __restrict__ row_base, const int* __restrict__ row_cnt,
       const float* __restrict__ dinv,
       const float* __restrict__ bias, const float* __restrict__ sW,
       const float* __restrict__ sb,
       const float* __restrict__ bg, const float* __restrict__ bb,
       const float* __restrict__ bm, const float* __restrict__ bv,
       int nper, int k,
       int* __restrict__ remap,
       float* __restrict__ hp /*null for layer 1*/, float* __restrict__ pooled,
       int write_remap,
       const float* __restrict__ pool0, const float* __restrict__ pool1,
       const float* __restrict__ lW0, const float* __restrict__ lb0,
       const float* __restrict__ lW1, const float* __restrict__ lb1,
       const float* __restrict__ lW2, const float* __restrict__ lb2,
       float* __restrict__ finout) {
    extern __shared__ float stage[];   // [nper*64 floats stage][EPGP ints csr_s]
    __shared__ float di_s[512];
    __shared__ float tdi_s[512];
    __shared__ float hsdi_s[512];
    __shared__ float sc_s[512];
    __shared__ float tn_s[512];
    __shared__ int   inv_s[512];
    __shared__ int   rb_s[512];
    __shared__ int   rc_s[512];
    __shared__ int   wsum16[16];
    __shared__ int   scr[1024];
    __shared__ float bnA[HF];
    __shared__ float bnC[HF];
    __shared__ float pool_s[HF];
    __shared__ float bs_sh;
    float* fpart = (float*)scr;

    int g = blockIdx.x, tid = threadIdx.x;
    int lane = tid & 31, wid = tid >> 5;
    int node = tid & 511, half = tid >> 9;
    int gbase = g * nper;
    int* csr_sm = (int*)(stage + nper * 64);

    if (tid < HF) {
        float A = bg[tid] * rsqrtf(bv[tid] + BN_EPS);
        bnA[tid] = A;
        bnC[tid] = bb[tid] - A * bm[tid];
        pool_s[tid] = 0.f;
    }
    if (tid < 512) {
        bool in = tid < nper;
        di_s[tid] = in ? dinv[gbase + tid] : 0.f;
        rb_s[tid] = in ? row_base[gbase + tid] : 0;
        rc_s[tid] = in ? row_cnt[gbase + tid] : 0;
    }
    if (wid == 31) {   // bs = conv_bias · score_W
        float a = 0.f;
        #pragma unroll
        for (int f = lane; f < HF; f += 32) a += bias[f] * sW[f];
        #pragma unroll
        for (int off = 16; off > 0; off >>= 1) a += __shfl_down_sync(0xFFFFFFFFu, a, off);
        if (lane == 0) bs_sh = a;
    }
    {
        int4* dstv = (int4*)csr_sm;
        const int4* srcv = (const int4*)(csr + (size_t)g * EPGP);
        for (int i = tid; i < EPGP / 4; i += 1024) dstv[i] = srcv[i];
    }
    __syncthreads();   // di_s ready for staging scale

    // ---- EARLY: stage chunk 0 (features 0..63), overlaps with scalar phases ----
    for (int i2 = tid; i2 < nper * 16; i2 += 1024) {
        int row = i2 >> 4, f4 = (i2 & 15) * 4;
        float4 vv = *(const float4*)(H + (size_t)(gbase + row) * HF + f4);
        float d = di_s[row];
        vv.x *= d; vv.y *= d; vv.z *= d; vv.w *= d;
        *(float4*)(&stage[row * 64 + f4]) = vv;
    }
    // no sync needed yet: stage not read until kept sweep; sync happens before then

    // ---- t-pass ----
    {
        float4 wv4 = *(const float4*)(sW + lane * 4);
        for (int v = wid; v < nper; v += 32) {
            float4 h = *(const float4*)(H + (size_t)(gbase + v) * HF + lane * 4);
            float p = h.x * wv4.x + h.y * wv4.y + h.z * wv4.z + h.w * wv4.w;
            #pragma unroll
            for (int off = 16; off > 0; off >>= 1) p += __shfl_down_sync(0xFFFFFFFFu, p, off);
            if (lane == 0) tdi_s[v] = p * di_s[v];
        }
    }
    __syncthreads();

    // ---- hs sweep (2 threads per node) ----
    {
        float part = 0.f;
        if (node < nper) {
            int base = rb_s[node], cnt = rc_s[node];
            const int* cp = csr_sm + base;
            const char* hb = (const char*)tdi_s;
            for (int e = half * 4; e + 4 <= cnt; e += 8) {
                int4 o = *(const int4*)(cp + e);
                part += *(const float*)(hb + (o.x >> 6)) + *(const float*)(hb + (o.y >> 6))
                      + *(const float*)(hb + (o.z >> 6)) + *(const float*)(hb + (o.w >> 6));
            }
            if (half == 0)
                for (int e = cnt & ~3; e < cnt; e++)
                    part += *(const float*)(hb + (cp[e] >> 6));
        }
        fpart[tid] = part;
        __syncthreads();
        if (tid < nper) {
            float di = di_s[tid];
            float hs = (fpart[tid] + fpart[tid + 512] + tdi_s[tid]) * di + bs_sh;
            hsdi_s[tid] = hs * di;
        } else if (tid < 512) hsdi_s[tid] = 0.f;
        __syncthreads();
    }

    // ---- score sweep (split) ----
    float scv = -1e30f;
    {
        float part = 0.f;
        if (node < nper) {
            int base = rb_s[node], cnt = rc_s[node];
            const int* cp = csr_sm + base;
            const char* hb = (const char*)hsdi_s;
            for (int e = half * 4; e + 4 <= cnt; e += 8) {
                int4 o = *(const int4*)(cp + e);
                part += *(const float*)(hb + (o.x >> 6)) + *(const float*)(hb + (o.y >> 6))
                      + *(const float*)(hb + (o.z >> 6)) + *(const float*)(hb + (o.w >> 6));
            }
            if (half == 0)
                for (int e = cnt & ~3; e < cnt; e++)
                    part += *(const float*)(hb + (cp[e] >> 6));
        }
        fpart[tid] = part;
        __syncthreads();
        if (tid < nper) {
            float di = di_s[tid];
            scv = (fpart[tid] + fpart[tid + 512] + hsdi_s[tid]) * di + sb[0];
        }
        if (tid < 512) sc_s[tid] = scv;
        __syncthreads();
    }

    // ---- rank (split halves) ----
    int kept = 0;
    {
        float si = sc_s[node];
        int r = 0;
        const float4* sc4 = (const float4*)sc_s;
        int j0 = half * 64;
        for (int j4 = j0; j4 < j0 + 64; j4++) {
            float4 pj = sc4[j4];
            int b4 = 4 * j4;
            r += (pj.x > si) || (pj.x == si && (b4)     < node);
            r += (pj.y > si) || (pj.y == si && (b4 + 1) < node);
            r += (pj.z > si) || (pj.z == si && (b4 + 2) < node);
            r += (pj.w > si) || (pj.w == si && (b4 + 3) < node);
        }
        scr[tid] = r;
        __syncthreads();
        if (tid < 512) {
            int rank = scr[tid] + scr[tid + 512];
            kept = (tid < nper && rank < k) ? 1 : 0;
        }
    }

    // ---- warp-shuffle scan over 512 ----
    int v = kept;
    if (tid < 512) {
        #pragma unroll
        for (int d2 = 1; d2 < 32; d2 <<= 1) {
            int t = __shfl_up_sync(0xFFFFFFFFu, v, d2);
            if (lane >= d2) v += t;
        }
        if (lane == 31) wsum16[wid] = v;
    }
    __syncthreads();
    if (tid < 16) {
        int w = wsum16[tid];
        #pragma unroll
        for (int d2 = 1; d2 < 16; d2 <<= 1) {
            int t = __shfl_up_sync(0xFFFFu, w, d2);
            if (tid >= d2) w += t;
        }
        wsum16[tid] = w;
    }
    __syncthreads();
    if (tid < nper) {
        int incl = v + ((wid > 0) ? wsum16[wid - 1] : 0);
        int pos = incl - 1;
        if (write_remap) remap[gbase + tid] = kept ? (g * k + pos) : -1;
        if (kept) {
            inv_s[pos] = tid;
            tn_s[pos]  = tanhf(scv);
        }
    }
    __syncthreads();

    // ---- two feature-chunk passes: aggregate KEPT rows only ----
    #pragma unroll 1
    for (int cf = 0; cf < HF; cf += 64) {
        if (cf > 0) {
            // restage chunk 1 (chunk 0 was staged early)
            for (int i2 = tid; i2 < nper * 16; i2 += 1024) {
                int row = i2 >> 4, f4 = (i2 & 15) * 4;
                float4 vv = *(const float4*)(H + (size_t)(gbase + row) * HF + cf + f4);
                float d = di_s[row];
                vv.x *= d; vv.y *= d; vv.z *= d; vv.w *= d;
                *(float4*)(&stage[row * 64 + f4]) = vv;
            }
            __syncthreads();
        }
        int fp = 2 * lane;
        const char* sf = (const char*)stage + fp * 4;
        float2 bp = *(const float2*)(bias + cf + fp);
        float2 bA = *(const float2*)(bnA + cf + fp);
        float2 bC = *(const float2*)(bnC + cf + fp);
        float s0 = 0.f, s1 = 0.f;
        for (int rn = wid; rn < k; rn += 32) {
            int old = inv_s[rn];
            int base = rb_s[old], cnt = rc_s[old];
            const int* cp = csr_sm + base;
            u64 A0 = *(const u64*)(sf + old * 256);
            u64 A1 = 0, A2 = 0, A3 = 0;
            int e = 0;
            for (; e + 8 <= cnt; e += 8) {
                int4 o0 = *(const int4*)(cp + e);
                int4 o1 = *(const int4*)(cp + e + 4);
                A0 = fadd2(A0, *(const u64*)(sf + o0.x));
                A1 = fadd2(A1, *(const u64*)(sf + o0.y));
                A2 = fadd2(A2, *(const u64*)(sf + o0.z));
                A3 = fadd2(A3, *(const u64*)(sf + o0.w));
                A0 = fadd2(A0, *(const u64*)(sf + o1.x));
                A1 = fadd2(A1, *(const u64*)(sf + o1.y));
                A2 = fadd2(A2, *(const u64*)(sf + o1.z));
                A3 = fadd2(A3, *(const u64*)(sf + o1.w));
            }
            for (; e + 4 <= cnt; e += 4) {
                int4 o = *(const int4*)(cp + e);
                A0 = fadd2(A0, *(const u64*)(sf + o.x));
                A1 = fadd2(A1, *(const u64*)(sf + o.y));
                A2 = fadd2(A2, *(const u64*)(sf + o.z));
                A3 = fadd2(A3, *(const u64*)(sf + o.w));
            }
            for (; e < cnt; e++)
                A0 = fadd2(A0, *(const u64*)(sf + cp[e]));
            A0 = fadd2(fadd2(A0, A1), fadd2(A2, A3));
            float2 r0 = *(float2*)&A0;
            float d = di_s[old];
            float tv = tn_s[rn];
            float o0 = r0.x * d + bp.x;
            float o1 = r0.y * d + bp.y;
            float q0 = fmaxf(bA.x * (o0 * tv) + bC.x, 0.f);
            float q1 = fmaxf(bA.y * (o1 * tv) + bC.y, 0.f);
            if (hp)
                *(float2*)(hp + ((size_t)g * k + rn) * HF + cf + fp) = make_float2(q0, q1);
            s0 += q0; s1 += q1;
        }
        atomicAdd(&pool_s[cf + fp],     s0);
        atomicAdd(&pool_s[cf + fp + 1], s1);
        __syncthreads();
    }
    if (tid < HF) pooled[g * HF + tid] = pool_s[tid];

    // ---- fused readout (layer 1 only) ----
    if (finout && wid < DOUT) {
        int o = wid;
        const float* p0g = pool0 + g * HF;
        const float* p1g = pool1 + g * HF;
        const float* w0 = lW0 + o * HF;
        const float* w1 = lW1 + o * HF;
        const float* w2 = lW2 + o * HF;
        float a = 0.f;
        #pragma unroll
        for (int f = lane; f < HF; f += 32)
            a += p0g[f] * w0[f] + p1g[f] * w1[f] + pool_s[f] * w2[f];
        #pragma unroll
        for (int off = 16; off > 0; off >>= 1) a += __shfl_down_sync(0xFFFFFFFFu, a, off);
        if (lane == 0) finout[g * DOUT + o] = a + lb0[o] + lb1[o] + lb2[o];
    }
}

// ---------------- host launch ----------------
extern "C" void kernel_launch(void* const* d_in, const int* in_sizes, int n_in,
                              void* d_out, int out_size) {
    const float* x        = (const float*)d_in[0];
    const int*   ei       = (const int*)  d_in[1];
    const float* conv1_W  = (const float*)d_in[2];
    const float* conv1_b  = (const float*)d_in[3];
    const float* conv2_W  = (const float*)d_in[4];
    const float* conv2_b  = (const float*)d_in[5];
    const float* score1_W = (const float*)d_in[6];
    const float* score1_b = (const float*)d_in[7];
    const float* score2_W = (const float*)d_in[8];
    const float* score2_b = (const float*)d_in[9];
    const float* bn1_g    = (const float*)d_in[10];
    const float* bn1_b    = (const float*)d_in[11];
    const float* bn1_m    = (const float*)d_in[12];
    const float* bn1_v    = (const float*)d_in[13];
    const float* bn2_g    = (const float*)d_in[14];
    const float* bn2_b    = (const float*)d_in[15];
    const float* bn2_m    = (const float*)d_in[16];
    const float* bn2_v    = (const float*)d_in[17];
    const float* lin0_W   = (const float*)d_in[18];
    const float* lin0_b   = (const float*)d_in[19];
    const float* lin1_W   = (const float*)d_in[20];
    const float* lin1_b   = (const float*)d_in[21];
    const float* lin2_W   = (const float*)d_in[22];
    const float* lin2_b   = (const float*)d_in[23];
    float* out = (float*)d_out;

    const int* src0 = ei;
    const int* dst0 = ei + EE;

    float *bufB, *bufC, *dinv, *pool;
    int *remap, *rowbase, *rowcnt, *csrsrc;
    u64 *wp1, *wp2;
    cudaGetSymbolAddress((void**)&bufB,   g_bufB);
    cudaGetSymbolAddress((void**)&bufC,   g_bufC);
    cudaGetSymbolAddress((void**)&dinv,   g_dinv);
    cudaGetSymbolAddress((void**)&remap,  g_remap);
    cudaGetSymbolAddress((void**)&rowbase,g_rowbase);
    cudaGetSymbolAddress((void**)&rowcnt, g_rowcnt);
    cudaGetSymbolAddress((void**)&csrsrc, g_csrsrc);
    cudaGetSymbolAddress((void**)&wp1,    g_Wp1);
    cudaGetSymbolAddress((void**)&wp2,    g_Wp2);
    cudaGetSymbolAddress((void**)&pool,   g_pool);

    const int COMB_SMEM  = 41088;                          // csr carve (gemm uses 32 KB)
    const int MEGA_SMEM0 = (NPER0 * 64) * 4 + EPGP * 4;    // 168 KB
    const int MEGA_SMEM1 = (K1 * 64) * 4 + EPGP * 4;       // ~142.5 KB
    cudaFuncSetAttribute(k_mega, cudaFuncAttributeMaxDynamicSharedMemorySize, MEGA_SMEM0);

    k_packW2<<<(2 * 64 * HF + 255) / 256, 256>>>(conv1_W, conv2_W, wp1, wp2);

    // ---------- layer 0: csr0 | pooled_x | gemm0 in one launch ----------
    k_comb_g0<<<2 * BGR + N0 / 64, 256, COMB_SMEM>>>(x, wp1, bufB, pool,
                                                     src0, dst0, rowbase, rowcnt,
                                                     csrsrc, dinv);
    k_mega<<<BGR, 1024, MEGA_SMEM0>>>(bufB, csrsrc, rowbase, rowcnt, dinv,
                                      conv1_b, score1_W, score1_b,
                                      bn1_g, bn1_b, bn1_m, bn1_v,
                                      NPER0, K1, remap, bufC,
                                      pool + BGR * HF, 1,
                                      nullptr, nullptr, nullptr, nullptr,
                                      nullptr, nullptr, nullptr, nullptr, nullptr);

    // ---------- layer 1: csr1 | gemm1 in one launch; readout fused in mega ----
    k_comb_g1<<<BGR + N1 / 64, 256, COMB_SMEM>>>(bufC, wp2, bufB,
                                                 src0, dst0, remap, rowbase, rowcnt,
                                                 csrsrc, dinv);
    k_mega<<<BGR, 1024, MEGA_SMEM1>>>(bufB, csrsrc, rowbase, rowcnt, dinv,
                                      conv2_b, score2_W, score2_b,
                                      bn2_g, bn2_b, bn2_m, bn2_v,
                                      K1, K2, remap, nullptr,
                                      pool + 2 * BGR * HF, 0,
                                      pool, pool + BGR * HF,
                                      lin0_W, lin0_b, lin1_W, lin1_b, lin2_W, lin2_b,
                                      out);
}

// round 15
// speedup vs baseline: 1.1410x; 1.0494x over previous
#include <cuda_runtime.h>
#include <math.h>
#include <stdint.h>

// ---------------- problem constants ----------------
#define BGR   128
#define NPER0 512
#define EPG   8192
#define EPGP  10240        // padded csr stride per graph
#define EE    (BGR*EPG)
#define N0    (BGR*NPER0)  // 65536
#define K1    410
#define K2    328
#define N1    (BGR*K1)     // 52480
#define HF    128
#define DOUT  10
#define BN_EPS 1e-5f

typedef unsigned long long u64;

// ---------------- static device scratch ----------------
__device__ float g_bufB[(size_t)N0*HF];   // X@W
__device__ float g_bufC[(size_t)N1*HF];   // hp1
__device__ float g_dinv[N0];
__device__ int   g_remap[N0];
__device__ int   g_rowbase[N0];           // LOCAL offset within graph's csr
__device__ int   g_rowcnt[N0];
__device__ int   g_csrsrc[(size_t)BGR*EPGP];  // s_local<<8 (smem byte offset)
__device__ u64   g_Wp1[64*HF];            // lane-dense packed layout (see k_packW2)
__device__ u64   g_Wp2[64*HF];
__device__ float g_pool[3*BGR*HF];

__device__ __forceinline__ u64 ffma2(u64 a, u64 b, u64 c) {
    u64 d;
    asm("fma.rn.f32x2 %0, %1, %2, %3;" : "=l"(d) : "l"(a), "l"(b), "l"(c));
    return d;
}
__device__ __forceinline__ u64 fadd2(u64 a, u64 b) {
    u64 d;
    asm("add.rn.f32x2 %0, %1, %2;" : "=l"(d) : "l"(a), "l"(b));
    return d;
}

// ---------------- pack both weight matrices (lane-dense layout) ----------------
// Per kp (128 u64 = 1KB):
//   [0..63]   : lane L gets w(kp, 4L), w(kp, 4L+1)    at offset L*2
//   [64..127] : lane L gets w(kp, 4L+2), w(kp, 4L+3)  at offset 64 + L*2
// => every warp LDG.128 covers a dense 512B region (4 wavefronts, not 8).
__global__ void k_packW2(const float* __restrict__ W1, const float* __restrict__ W2,
                         u64* __restrict__ Wp1, u64* __restrict__ Wp2) {
    int i = blockIdx.x * blockDim.x + threadIdx.x;
    const int n = 64 * HF;
    if (i >= 2 * n) return;
    const float* W = (i < n) ? W1 : W2;
    u64* Wp = (i < n) ? Wp1 : Wp2;
    int j = (i < n) ? i : i - n;
    int kp = j >> 7, t = j & 127;
    int col;
    if (t < 64) { int L = t >> 1, h = t & 1; col = 4 * L + h; }
    else        { int t2 = t - 64; int L = t2 >> 1, h = t2 & 1; col = 4 * L + 2 + h; }
    u64 lo = __float_as_uint(W[(2 * kp) * HF + col]);
    u64 hi = __float_as_uint(W[(2 * kp + 1) * HF + col]);
    Wp[j] = lo | (hi << 32);
}

// ---------------- CSR build, 256 threads, carved from dynamic smem ------------
__device__ __forceinline__
void dev_csr256(int g, const int* __restrict__ src, const int* __restrict__ dst,
                const int* __restrict__ remap, int nper_dst,
                int* __restrict__ row_base, int* __restrict__ row_cnt,
                int* __restrict__ csr, float* __restrict__ dinv, char* dsm) {
    unsigned* ed  = (unsigned*)dsm;
    int* cnt  = (int*)(dsm + 32768);
    int* off  = cnt + 512;
    int* cur  = off + 512;
    int* rms  = cur + 512;
    int* wsum8 = rms + 512;
    int tid = threadIdx.x, lane = tid & 31, wid = tid >> 5;
    cnt[tid] = 0; cnt[tid + 256] = 0;
    cur[tid] = 0; cur[tid + 256] = 0;
    if (remap) {
        rms[tid]       = remap[g * NPER0 + tid];
        rms[tid + 256] = remap[g * NPER0 + tid + 256];
    }
    __syncthreads();
    int ebase = g * EPG, gdst = g * nper_dst;
    for (int e = tid; e < EPG; e += 256) {
        int s = src[ebase + e] - g * NPER0;
        int d = dst[ebase + e] - g * NPER0;
        unsigned pk = 0xFFFFFFFFu;
        if (remap) {
            int rs = rms[s], rd = rms[d];
            if ((rs | rd) >= 0)
                pk = ((unsigned)(rs - gdst) << 16) | (unsigned)(rd - gdst);
        } else {
            pk = ((unsigned)s << 16) | (unsigned)d;
        }
        ed[e] = pk;
        if (pk != 0xFFFFFFFFu) atomicAdd(&cnt[pk & 0xFFFFu], 1);
    }
    __syncthreads();
    int c0 = cnt[2 * tid], c1 = cnt[2 * tid + 1];
    int pc0 = (c0 + 3) & ~3, pc1 = (c1 + 3) & ~3;
    int v = pc0 + pc1;
    #pragma unroll
    for (int d2 = 1; d2 < 32; d2 <<= 1) {
        int t = __shfl_up_sync(0xFFFFFFFFu, v, d2);
        if (lane >= d2) v += t;
    }
    if (lane == 31) wsum8[wid] = v;
    __syncthreads();
    if (tid < 8) {
        int w = wsum8[tid];
        #pragma unroll
        for (int d2 = 1; d2 < 8; d2 <<= 1) {
            int t = __shfl_up_sync(0xFFu, w, d2);
            if (tid >= d2) w += t;
        }
        wsum8[tid] = w;
    }
    __syncthreads();
    int excl = v - (pc0 + pc1) + ((wid > 0) ? wsum8[wid - 1] : 0);
    int ebp = g * EPGP;
    int n0 = 2 * tid, n1 = 2 * tid + 1;
    if (n0 < nper_dst) {
        row_cnt[gdst + n0]  = c0;
        row_base[gdst + n0] = excl;
        dinv[gdst + n0]     = rsqrtf(1.0f + (float)c0);
    }
    if (n1 < nper_dst) {
        row_cnt[gdst + n1]  = c1;
        row_base[gdst + n1] = excl + pc0;
        dinv[gdst + n1]     = rsqrtf(1.0f + (float)c1);
    }
    off[n0] = excl; off[n1] = excl + pc0;
    __syncthreads();
    for (int e = tid; e < EPG; e += 256) {
        unsigned pk = ed[e];
        if (pk != 0xFFFFFFFFu) {
            int d = pk & 0xFFFFu, s = pk >> 16;
            int p = atomicAdd(&cur[d], 1);
            csr[ebp + off[d] + p] = s << 8;
        }
    }
}

// ---------------- GEMM v5: 64-row tile, lane-dense W loads ----------------
// Same 8-row x 4-col micro-tile; W reads now dense (4 wf/LDG vs 8).
__device__ __forceinline__
void dev_gemm(int tile, const float* __restrict__ X, const u64* __restrict__ Wp,
              float* __restrict__ Y, float (*Xs)[HF]) {
    int row0 = tile * 64;
    int tid = threadIdx.x;
    #pragma unroll
    for (int j = 0; j < 8; j++) {
        int idx = j * 256 + tid;
        int r = idx >> 5, c4 = idx & 31;
        float4 v = *(const float4*)(X + (size_t)(row0 + r) * HF + c4 * 4);
        *(float4*)(&Xs[r][c4 * 4]) = v;
    }
    __syncthreads();
    int wid = tid >> 5, lane = tid & 31;
    int r0 = wid * 8, c0 = lane * 4;
    u64 acc[8][4] = {};
    #pragma unroll 1
    for (int kp4 = 0; kp4 < 16; kp4++) {
        const u64* wb = Wp + (size_t)(kp4 * 4) * HF;
        // lane-dense: wA_j at j*128 + lane*2 (cols 4L,4L+1); wB_j at +64 (cols 4L+2,4L+3)
        ulonglong2 wA0 = *(const ulonglong2*)(wb +             lane * 2);
        ulonglong2 wB0 = *(const ulonglong2*)(wb +        64 + lane * 2);
        ulonglong2 wA1 = *(const ulonglong2*)(wb + 128 +       lane * 2);
        ulonglong2 wB1 = *(const ulonglong2*)(wb + 128 +  64 + lane * 2);
        ulonglong2 wA2 = *(const ulonglong2*)(wb + 256 +       lane * 2);
        ulonglong2 wB2 = *(const ulonglong2*)(wb + 256 +  64 + lane * 2);
        ulonglong2 wA3 = *(const ulonglong2*)(wb + 384 +       lane * 2);
        ulonglong2 wB3 = *(const ulonglong2*)(wb + 384 +  64 + lane * 2);
        #pragma unroll
        for (int i = 0; i < 8; i++) {
            ulonglong2 xa = *(const ulonglong2*)(&Xs[r0 + i][kp4 * 8]);
            ulonglong2 xb = *(const ulonglong2*)(&Xs[r0 + i][kp4 * 8 + 4]);
            acc[i][0] = ffma2(xa.x, wA0.x, acc[i][0]);
            acc[i][1] = ffma2(xa.x, wA0.y, acc[i][1]);
            acc[i][2] = ffma2(xa.x, wB0.x, acc[i][2]);
            acc[i][3] = ffma2(xa.x, wB0.y, acc[i][3]);
            acc[i][0] = ffma2(xa.y, wA1.x, acc[i][0]);
            acc[i][1] = ffma2(xa.y, wA1.y, acc[i][1]);
            acc[i][2] = ffma2(xa.y, wB1.x, acc[i][2]);
            acc[i][3] = ffma2(xa.y, wB1.y, acc[i][3]);
            acc[i][0] = ffma2(xb.x, wA2.x, acc[i][0]);
            acc[i][1] = ffma2(xb.x, wA2.y, acc[i][1]);
            acc[i][2] = ffma2(xb.x, wB2.x, acc[i][2]);
            acc[i][3] = ffma2(xb.x, wB2.y, acc[i][3]);
            acc[i][0] = ffma2(xb.y, wA3.x, acc[i][0]);
            acc[i][1] = ffma2(xb.y, wA3.y, acc[i][1]);
            acc[i][2] = ffma2(xb.y, wB3.x, acc[i][2]);
            acc[i][3] = ffma2(xb.y, wB3.y, acc[i][3]);
        }
    }
    #pragma unroll
    for (int i = 0; i < 8; i++) {
        int r = row0 + r0 + i;
        float2 p0 = *(float2*)&acc[i][0];
        float2 p1 = *(float2*)&acc[i][1];
        float2 p2 = *(float2*)&acc[i][2];
        float2 p3 = *(float2*)&acc[i][3];
        float4 o = make_float4(p0.x + p0.y, p1.x + p1.y, p2.x + p2.y, p3.x + p3.y);
        *(float4*)(Y + (size_t)r * HF + c0) = o;
    }
}

// ---------------- layer-0 combined: csr0 | pooled_x | gemm0 -------------------
__global__ void __launch_bounds__(256, 2)
k_comb_g0(const float* __restrict__ x, const u64* __restrict__ Wp1,
          float* __restrict__ bufB, float* __restrict__ P0,
          const int* __restrict__ src, const int* __restrict__ dst,
          int* __restrict__ rowbase, int* __restrict__ rowcnt,
          int* __restrict__ csr, float* __restrict__ dinv) {
    extern __shared__ char dsm[];
    int bid = blockIdx.x;
    if (bid < BGR) {
        dev_csr256(bid, src, dst, nullptr, NPER0, rowbase, rowcnt, csr, dinv, dsm);
    } else if (bid < 2 * BGR) {
        int g = bid - BGR;
        float* red = (float*)dsm;
        int f = threadIdx.x & 127, q = threadIdx.x >> 7;
        const float* base = x + (size_t)g * NPER0 * HF + f;
        float acc = 0.f;
        for (int r = q; r < NPER0; r += 2) acc += base[(size_t)r * HF];
        red[q * HF + f] = acc;
        __syncthreads();
        if (q == 0) P0[g * HF + f] = red[f] + red[HF + f];
    } else {
        dev_gemm(bid - 2 * BGR, x, Wp1, bufB, (float(*)[HF])dsm);
    }
}

// ---------------- layer-1 combined: csr1 | gemm1 -------------------
__global__ void __launch_bounds__(256, 2)
k_comb_g1(const float* __restrict__ X, const u64* __restrict__ Wp2,
          float* __restrict__ Y,
          const int* __restrict__ src, const int* __restrict__ dst,
          const int* __restrict__ remap,
          int* __restrict__ rowbase, int* __restrict__ rowcnt,
          int* __restrict__ csr, float* __restrict__ dinv) {
    extern __shared__ char dsm[];
    int bid = blockIdx.x;
    if (bid < BGR) {
        dev_csr256(bid, src, dst, remap, K1, rowbase, rowcnt, csr, dinv, dsm);
    } else {
        dev_gemm(bid - BGR, X, Wp2, Y, (float(*)[HF])dsm);
    }
}

// ================= MEGA v8: chunk-0 staged early (overlaps scalar phases) =====
__global__ void __launch_bounds__(1024, 1)
k_mega(const float* __restrict__ H,
       const int* __restrict__ csr,
       const int* __restrict__ row_base, const int* __restrict__ row_cnt,
       const float* __restrict__ dinv,
       const float* __restrict__ bias, const float* __restrict__ sW,
       const float* __restrict__ sb,
       const float* __restrict__ bg, const float* __restrict__ bb,
       const float* __restrict__ bm, const float* __restrict__ bv,
       int nper, int k,
       int* __restrict__ remap,
       float* __restrict__ hp /*null for layer 1*/, float* __restrict__ pooled,
       int write_remap,
       const float* __restrict__ pool0, const float* __restrict__ pool1,
       const float* __restrict__ lW0, const float* __restrict__ lb0,
       const float* __restrict__ lW1, const float* __restrict__ lb1,
       const float* __restrict__ lW2, const float* __restrict__ lb2,
       float* __restrict__ finout) {
    extern __shared__ float stage[];   // [nper*64 floats stage][EPGP ints csr_s]
    __shared__ float di_s[512];
    __shared__ float tdi_s[512];
    __shared__ float hsdi_s[512];
    __shared__ float sc_s[512];
    __shared__ float tn_s[512];
    __shared__ int   inv_s[512];
    __shared__ int   rb_s[512];
    __shared__ int   rc_s[512];
    __shared__ int   wsum16[16];
    __shared__ int   scr[1024];
    __shared__ float bnA[HF];
    __shared__ float bnC[HF];
    __shared__ float pool_s[HF];
    __shared__ float bs_sh;
    float* fpart = (float*)scr;

    int g = blockIdx.x, tid = threadIdx.x;
    int lane = tid & 31, wid = tid >> 5;
    int node = tid & 511, half = tid >> 9;
    int gbase = g * nper;
    int* csr_sm = (int*)(stage + nper * 64);

    if (tid < HF) {
        float A = bg[tid] * rsqrtf(bv[tid] + BN_EPS);
        bnA[tid] = A;
        bnC[tid] = bb[tid] - A * bm[tid];
        pool_s[tid] = 0.f;
    }
    if (tid < 512) {
        bool in = tid < nper;
        di_s[tid] = in ? dinv[gbase + tid] : 0.f;
        rb_s[tid] = in ? row_base[gbase + tid] : 0;
        rc_s[tid] = in ? row_cnt[gbase + tid] : 0;
    }
    if (wid == 31) {   // bs = conv_bias · score_W
        float a = 0.f;
        #pragma unroll
        for (int f = lane; f < HF; f += 32) a += bias[f] * sW[f];
        #pragma unroll
        for (int off = 16; off > 0; off >>= 1) a += __shfl_down_sync(0xFFFFFFFFu, a, off);
        if (lane == 0) bs_sh = a;
    }
    {
        int4* dstv = (int4*)csr_sm;
        const int4* srcv = (const int4*)(csr + (size_t)g * EPGP);
        for (int i = tid; i < EPGP / 4; i += 1024) dstv[i] = srcv[i];
    }
    __syncthreads();   // di_s ready for staging scale

    // ---- EARLY: stage chunk 0, overlaps with scalar phases ----
    for (int i2 = tid; i2 < nper * 16; i2 += 1024) {
        int row = i2 >> 4, f4 = (i2 & 15) * 4;
        float4 vv = *(const float4*)(H + (size_t)(gbase + row) * HF + f4);
        float d = di_s[row];
        vv.x *= d; vv.y *= d; vv.z *= d; vv.w *= d;
        *(float4*)(&stage[row * 64 + f4]) = vv;
    }

    // ---- t-pass ----
    {
        float4 wv4 = *(const float4*)(sW + lane * 4);
        for (int v = wid; v < nper; v += 32) {
            float4 h = *(const float4*)(H + (size_t)(gbase + v) * HF + lane * 4);
            float p = h.x * wv4.x + h.y * wv4.y + h.z * wv4.z + h.w * wv4.w;
            #pragma unroll
            for (int off = 16; off > 0; off >>= 1) p += __shfl_down_sync(0xFFFFFFFFu, p, off);
            if (lane == 0) tdi_s[v] = p * di_s[v];
        }
    }
    __syncthreads();

    // ---- hs sweep (2 threads per node) ----
    {
        float part = 0.f;
        if (node < nper) {
            int base = rb_s[node], cnt = rc_s[node];
            const int* cp = csr_sm + base;
            const char* hb = (const char*)tdi_s;
            for (int e = half * 4; e + 4 <= cnt; e += 8) {
                int4 o = *(const int4*)(cp + e);
                part += *(const float*)(hb + (o.x >> 6)) + *(const float*)(hb + (o.y >> 6))
                      + *(const float*)(hb + (o.z >> 6)) + *(const float*)(hb + (o.w >> 6));
            }
            if (half == 0)
                for (int e = cnt & ~3; e < cnt; e++)
                    part += *(const float*)(hb + (cp[e] >> 6));
        }
        fpart[tid] = part;
        __syncthreads();
        if (tid < nper) {
            float di = di_s[tid];
            float hs = (fpart[tid] + fpart[tid + 512] + tdi_s[tid]) * di + bs_sh;
            hsdi_s[tid] = hs * di;
        } else if (tid < 512) hsdi_s[tid] = 0.f;
        __syncthreads();
    }

    // ---- score sweep (split) ----
    float scv = -1e30f;
    {
        float part = 0.f;
        if (node < nper) {
            int base = rb_s[node], cnt = rc_s[node];
            const int* cp = csr_sm + base;
            const char* hb = (const char*)hsdi_s;
            for (int e = half * 4; e + 4 <= cnt; e += 8) {
                int4 o = *(const int4*)(cp + e);
                part += *(const float*)(hb + (o.x >> 6)) + *(const float*)(hb + (o.y >> 6))
                      + *(const float*)(hb + (o.z >> 6)) + *(const float*)(hb + (o.w >> 6));
            }
            if (half == 0)
                for (int e = cnt & ~3; e < cnt; e++)
                    part += *(const float*)(hb + (cp[e] >> 6));
        }
        fpart[tid] = part;
        __syncthreads();
        if (tid < nper) {
            float di = di_s[tid];
            scv = (fpart[tid] + fpart[tid + 512] + hsdi_s[tid]) * di + sb[0];
        }
        if (tid < 512) sc_s[tid] = scv;
        __syncthreads();
    }

    // ---- rank (split halves) ----
    int kept = 0;
    {
        float si = sc_s[node];
        int r = 0;
        const float4* sc4 = (const float4*)sc_s;
        int j0 = half * 64;
        for (int j4 = j0; j4 < j0 + 64; j4++) {
            float4 pj = sc4[j4];
            int b4 = 4 * j4;
            r += (pj.x > si) || (pj.x == si && (b4)     < node);
            r += (pj.y > si) || (pj.y == si && (b4 + 1) < node);
            r += (pj.z > si) || (pj.z == si && (b4 + 2) < node);
            r += (pj.w > si) || (pj.w == si && (b4 + 3) < node);
        }
        scr[tid] = r;
        __syncthreads();
        if (tid < 512) {
            int rank = scr[tid] + scr[tid + 512];
            kept = (tid < nper && rank < k) ? 1 : 0;
        }
    }

    // ---- warp-shuffle scan over 512 ----
    int v = kept;
    if (tid < 512) {
        #pragma unroll
        for (int d2 = 1; d2 < 32; d2 <<= 1) {
            int t = __shfl_up_sync(0xFFFFFFFFu, v, d2);
            if (lane >= d2) v += t;
        }
        if (lane == 31) wsum16[wid] = v;
    }
    __syncthreads();
    if (tid < 16) {
        int w = wsum16[tid];
        #pragma unroll
        for (int d2 = 1; d2 < 16; d2 <<= 1) {
            int t = __shfl_up_sync(0xFFFFu, w, d2);
            if (tid >= d2) w += t;
        }
        wsum16[tid] = w;
    }
    __syncthreads();
    if (tid < nper) {
        int incl = v + ((wid > 0) ? wsum16[wid - 1] : 0);
        int pos = incl - 1;
        if (write_remap) remap[gbase + tid] = kept ? (g * k + pos) : -1;
        if (kept) {
            inv_s[pos] = tid;
            tn_s[pos]  = tanhf(scv);
        }
    }
    __syncthreads();

    // ---- two feature-chunk passes: aggregate KEPT rows only ----
    #pragma unroll 1
    for (int cf = 0; cf < HF; cf += 64) {
        if (cf > 0) {
            for (int i2 = tid; i2 < nper * 16; i2 += 1024) {
                int row = i2 >> 4, f4 = (i2 & 15) * 4;
                float4 vv = *(const float4*)(H + (size_t)(gbase + row) * HF + cf + f4);
                float d = di_s[row];
                vv.x *= d; vv.y *= d; vv.z *= d; vv.w *= d;
                *(float4*)(&stage[row * 64 + f4]) = vv;
            }
            __syncthreads();
        }
        int fp = 2 * lane;
        const char* sf = (const char*)stage + fp * 4;
        float2 bp = *(const float2*)(bias + cf + fp);
        float2 bA = *(const float2*)(bnA + cf + fp);
        float2 bC = *(const float2*)(bnC + cf + fp);
        float s0 = 0.f, s1 = 0.f;
        for (int rn = wid; rn < k; rn += 32) {
            int old = inv_s[rn];
            int base = rb_s[old], cnt = rc_s[old];
            const int* cp = csr_sm + base;
            u64 A0 = *(const u64*)(sf + old * 256);
            u64 A1 = 0, A2 = 0, A3 = 0;
            int e = 0;
            for (; e + 8 <= cnt; e += 8) {
                int4 o0 = *(const int4*)(cp + e);
                int4 o1 = *(const int4*)(cp + e + 4);
                A0 = fadd2(A0, *(const u64*)(sf + o0.x));
                A1 = fadd2(A1, *(const u64*)(sf + o0.y));
                A2 = fadd2(A2, *(const u64*)(sf + o0.z));
                A3 = fadd2(A3, *(const u64*)(sf + o0.w));
                A0 = fadd2(A0, *(const u64*)(sf + o1.x));
                A1 = fadd2(A1, *(const u64*)(sf + o1.y));
                A2 = fadd2(A2, *(const u64*)(sf + o1.z));
                A3 = fadd2(A3, *(const u64*)(sf + o1.w));
            }
            for (; e + 4 <= cnt; e += 4) {
                int4 o = *(const int4*)(cp + e);
                A0 = fadd2(A0, *(const u64*)(sf + o.x));
                A1 = fadd2(A1, *(const u64*)(sf + o.y));
                A2 = fadd2(A2, *(const u64*)(sf + o.z));
                A3 = fadd2(A3, *(const u64*)(sf + o.w));
            }
            for (; e < cnt; e++)
                A0 = fadd2(A0, *(const u64*)(sf + cp[e]));
            A0 = fadd2(fadd2(A0, A1), fadd2(A2, A3));
            float2 r0 = *(float2*)&A0;
            float d = di_s[old];
            float tv = tn_s[rn];
            float o0 = r0.x * d + bp.x;
            float o1 = r0.y * d + bp.y;
            float q0 = fmaxf(bA.x * (o0 * tv) + bC.x, 0.f);
            float q1 = fmaxf(bA.y * (o1 * tv) + bC.y, 0.f);
            if (hp)
                *(float2*)(hp + ((size_t)g * k + rn) * HF + cf + fp) = make_float2(q0, q1);
            s0 += q0; s1 += q1;
        }
        atomicAdd(&pool_s[cf + fp],     s0);
        atomicAdd(&pool_s[cf + fp + 1], s1);
        __syncthreads();
    }
    if (tid < HF) pooled[g * HF + tid] = pool_s[tid];

    // ---- fused readout (layer 1 only) ----
    if (finout && wid < DOUT) {
        int o = wid;
        const float* p0g = pool0 + g * HF;
        const float* p1g = pool1 + g * HF;
        const float* w0 = lW0 + o * HF;
        const float* w1 = lW1 + o * HF;
        const float* w2 = lW2 + o * HF;
        float a = 0.f;
        #pragma unroll
        for (int f = lane; f < HF; f += 32)
            a += p0g[f] * w0[f] + p1g[f] * w1[f] + pool_s[f] * w2[f];
        #pragma unroll
        for (int off = 16; off > 0; off >>= 1) a += __shfl_down_sync(0xFFFFFFFFu, a, off);
        if (lane == 0) finout[g * DOUT + o] = a + lb0[o] + lb1[o] + lb2[o];
    }
}

// ---------------- host launch ----------------
extern "C" void kernel_launch(void* const* d_in, const int* in_sizes, int n_in,
                              void* d_out, int out_size) {
    const float* x        = (const float*)d_in[0];
    const int*   ei       = (const int*)  d_in[1];
    const float* conv1_W  = (const float*)d_in[2];
    const float* conv1_b  = (const float*)d_in[3];
    const float* conv2_W  = (const float*)d_in[4];
    const float* conv2_b  = (const float*)d_in[5];
    const float* score1_W = (const float*)d_in[6];
    const float* score1_b = (const float*)d_in[7];
    const float* score2_W = (const float*)d_in[8];
    const float* score2_b = (const float*)d_in[9];
    const float* bn1_g    = (const float*)d_in[10];
    const float* bn1_b    = (const float*)d_in[11];
    const float* bn1_m    = (const float*)d_in[12];
    const float* bn1_v    = (const float*)d_in[13];
    const float* bn2_g    = (const float*)d_in[14];
    const float* bn2_b    = (const float*)d_in[15];
    const float* bn2_m    = (const float*)d_in[16];
    const float* bn2_v    = (const float*)d_in[17];
    const float* lin0_W   = (const float*)d_in[18];
    const float* lin0_b   = (const float*)d_in[19];
    const float* lin1_W   = (const float*)d_in[20];
    const float* lin1_b   = (const float*)d_in[21];
    const float* lin2_W   = (const float*)d_in[22];
    const float* lin2_b   = (const float*)d_in[23];
    float* out = (float*)d_out;

    const int* src0 = ei;
    const int* dst0 = ei + EE;

    float *bufB, *bufC, *dinv, *pool;
    int *remap, *rowbase, *rowcnt, *csrsrc;
    u64 *wp1, *wp2;
    cudaGetSymbolAddress((void**)&bufB,   g_bufB);
    cudaGetSymbolAddress((void**)&bufC,   g_bufC);
    cudaGetSymbolAddress((void**)&dinv,   g_dinv);
    cudaGetSymbolAddress((void**)&remap,  g_remap);
    cudaGetSymbolAddress((void**)&rowbase,g_rowbase);
    cudaGetSymbolAddress((void**)&rowcnt, g_rowcnt);
    cudaGetSymbolAddress((void**)&csrsrc, g_csrsrc);
    cudaGetSymbolAddress((void**)&wp1,    g_Wp1);
    cudaGetSymbolAddress((void**)&wp2,    g_Wp2);
    cudaGetSymbolAddress((void**)&pool,   g_pool);

    const int COMB_SMEM  = 41088;                          // csr carve (gemm uses 32 KB)
    const int MEGA_SMEM0 = (NPER0 * 64) * 4 + EPGP * 4;    // 168 KB
    const int MEGA_SMEM1 = (K1 * 64) * 4 + EPGP * 4;       // ~142.5 KB
    cudaFuncSetAttribute(k_mega, cudaFuncAttributeMaxDynamicSharedMemorySize, MEGA_SMEM0);

    k_packW2<<<(2 * 64 * HF + 255) / 256, 256>>>(conv1_W, conv2_W, wp1, wp2);

    // ---------- layer 0: csr0 | pooled_x | gemm0 in one launch ----------
    k_comb_g0<<<2 * BGR + N0 / 64, 256, COMB_SMEM>>>(x, wp1, bufB, pool,
                                                     src0, dst0, rowbase, rowcnt,
                                                     csrsrc, dinv);
    k_mega<<<BGR, 1024, MEGA_SMEM0>>>(bufB, csrsrc, rowbase, rowcnt, dinv,
                                      conv1_b, score1_W, score1_b,
                                      bn1_g, bn1_b, bn1_m, bn1_v,
                                      NPER0, K1, remap, bufC,
                                      pool + BGR * HF, 1,
                                      nullptr, nullptr, nullptr, nullptr,
                                      nullptr, nullptr, nullptr, nullptr, nullptr);

    // ---------- layer 1: csr1 | gemm1 in one launch; readout fused in mega ----
    k_comb_g1<<<BGR + N1 / 64, 256, COMB_SMEM>>>(bufC, wp2, bufB,
                                                 src0, dst0, remap, rowbase, rowcnt,
                                                 csrsrc, dinv);
    k_mega<<<BGR, 1024, MEGA_SMEM1>>>(bufB, csrsrc, rowbase, rowcnt, dinv,
                                      conv2_b, score2_W, score2_b,
                                      bn2_g, bn2_b, bn2_m, bn2_v,
                                      K1, K2, remap, nullptr,
                                      pool + 2 * BGR * HF, 0,
                                      pool, pool + BGR * HF,
                                      lin0_W, lin0_b, lin1_W, lin1_b, lin2_W, lin2_b,
                                      out);
}